// round 8
// baseline (speedup 1.0000x reference)
#include <cuda_runtime.h>
#include <cuda_fp16.h>
#include <cstdint>
#include <math.h>

#define D 32
#define H 128
#define THREADS 128
#define TILE_M 64
#define NROWS 65536

__device__ __forceinline__ uint32_t pack_h2(__half a, __half b) {
    return (uint32_t)__half_as_ushort(a) | ((uint32_t)__half_as_ushort(b) << 16);
}
__device__ __forceinline__ uint32_t cvt_h2(float a, float b) {
    // single F2FP.PACK: {fp16(a), fp16(b)}
    uint32_t r;
    asm("cvt.rn.f16x2.f32 %0, %2, %1;" : "=r"(r) : "f"(a), "f"(b));
    return r;
}
// fp16 2-way split of two fp32 values: v = h1 + h2 with |h2| ~ 2^-11 |v|
__device__ __forceinline__ void split2h(float vx, float vy, uint32_t& p1, uint32_t& p2) {
    __half hx = __float2half_rn(vx);
    __half hy = __float2half_rn(vy);
    float rx = vx - __half2float(hx);
    float ry = vy - __half2float(hy);
    p1 = pack_h2(hx, hy);
    p2 = cvt_h2(rx, ry);
}
__device__ __forceinline__ float tanh_ap(float x) {
    float y;
    asm("tanh.approx.f32 %0, %1;" : "=f"(y) : "f"(x));
    return y;
}
__device__ __forceinline__ void mma_f16(float* d, const uint32_t* a, uint32_t b0, uint32_t b1) {
    asm volatile(
        "mma.sync.aligned.m16n8k16.row.col.f32.f16.f16.f32 "
        "{%0,%1,%2,%3}, {%4,%5,%6,%7}, {%8,%9}, {%0,%1,%2,%3};"
        : "+f"(d[0]), "+f"(d[1]), "+f"(d[2]), "+f"(d[3])
        : "r"(a[0]), "r"(a[1]), "r"(a[2]), "r"(a[3]), "r"(b0), "r"(b1));
}

// ---------------- single fused kernel ----------------
extern "C" __global__ void __launch_bounds__(THREADS, 3)
stein_main(const float* __restrict__ x,
           const float* __restrict__ W1,
           const float* __restrict__ b1,
           const float* __restrict__ W2,
           const float* __restrict__ b2,
           const float* __restrict__ theta,
           float* __restrict__ out)
{
    __shared__ float s_base[TILE_M];
    __shared__ float s_cs[H];
    __shared__ float s_part[TILE_M][2];

    const int tid  = threadIdx.x;
    const int lane = tid & 31;
    const int w    = tid >> 5;
    const int mh   = w >> 1;        // row half (0: rows 0-31, 1: rows 32-63)
    const int kh   = w & 1;         // hidden-unit half (cols 0-63 / 64-127)
    const int row0 = blockIdx.x * TILE_M;

    // ---- c_k = sum_i W1[i,k] W2[k,i]  (coalesced W1 column reads) ----
    {
        const int k = tid;                          // 0..127
        const float4* w2r = (const float4*)(W2 + k * D);
        float c = 0.0f;
        #pragma unroll
        for (int i = 0; i < D; i += 4) {
            float4 wv = __ldg(w2r + (i >> 2));
            c = fmaf(__ldg(W1 + (i + 0) * H + k), wv.x, c);
            c = fmaf(__ldg(W1 + (i + 1) * H + k), wv.y, c);
            c = fmaf(__ldg(W1 + (i + 2) * H + k), wv.z, c);
            c = fmaf(__ldg(W1 + (i + 3) * H + k), wv.w, c);
        }
        s_cs[k] = c;
    }

    // ---- prologue: s_base[r] = theta - x[r].b2 (exact fp32) ----
    if (tid < TILE_M) {
        const float4* xr  = (const float4*)(x + (size_t)(row0 + tid) * D);
        const float4* b2v = (const float4*)b2;
        float s = __ldg(theta);
        #pragma unroll
        for (int i = 0; i < D / 4; i++) {
            float4 a = __ldg(xr + i);
            float4 b = __ldg(b2v + i);
            s = fmaf(-a.x, b.x, s);
            s = fmaf(-a.y, b.y, s);
            s = fmaf(-a.z, b.z, s);
            s = fmaf(-a.w, b.w, s);
        }
        s_base[tid] = s;
    }

    // ---- A fragments straight from gmem (frag order, fp16 h1/h2 split) ----
    const int Mbase = row0 + mh * 32;
    uint32_t a1[2][2][4], a2[2][2][4];           // [mt][ks][frag]
    #pragma unroll
    for (int mt = 0; mt < 2; mt++) {
        const int r = Mbase + mt * 16 + (lane >> 2);
        #pragma unroll
        for (int ks = 0; ks < 2; ks++) {
            const int c = ks * 16 + 2 * (lane & 3);
            float2 v00 = __ldg((const float2*)(x + (size_t)r       * D + c));
            float2 v10 = __ldg((const float2*)(x + (size_t)(r + 8) * D + c));
            float2 v01 = __ldg((const float2*)(x + (size_t)r       * D + c + 8));
            float2 v11 = __ldg((const float2*)(x + (size_t)(r + 8) * D + c + 8));
            split2h(v00.x, v00.y, a1[mt][ks][0], a2[mt][ks][0]);
            split2h(v10.x, v10.y, a1[mt][ks][1], a2[mt][ks][1]);
            split2h(v01.x, v01.y, a1[mt][ks][2], a2[mt][ks][2]);
            split2h(v11.x, v11.y, a1[mt][ks][3], a2[mt][ks][3]);
        }
    }
    __syncthreads();   // s_cs / s_base ready before epilogue reads

    // ---- per-lane weight pointers for inline B-frag build ----
    // z GEMM: B[n][k] = W1[k][n], n = kh*64 + p*8 + (lane>>2), k rows k0,k0+1,k0+8,k0+9
    // v GEMM: B[n][k] = W2[np][k], np = kh*64 + p*8 + (lane>>2), cols contiguous
    const int k0l = 2 * (lane & 3);
    const float* pz = W1 + (size_t)k0l * H + kh * 64 + (lane >> 2);   // advance +8 per p
    const float* pv = W2 + (size_t)(kh * 64 + (lane >> 2)) * D + k0l; // advance +8*D per p

    // ---- mainloop: per-p MMA slab (2-pass fp16), folded into psum ----
    float psum[4] = {0.f, 0.f, 0.f, 0.f};

    #pragma unroll 4
    for (int p = 0; p < 8; p++) {
        // --- build B frags inline (z side: scattered L1-hot; v side: float2) ---
        uint2 bz[2], bv[2];                       // [ks]
        #pragma unroll
        for (int ks = 0; ks < 2; ks++) {
            const float* pzk = pz + p * 8 + ks * 16 * H;
            bz[ks].x = cvt_h2(__ldg(pzk),         __ldg(pzk + H));        // rows k0, k0+1
            bz[ks].y = cvt_h2(__ldg(pzk + 8 * H), __ldg(pzk + 9 * H));    // rows k0+8, k0+9
            const float* pvk = pv + (size_t)p * 8 * D + ks * 16;
            float2 v0 = __ldg((const float2*)(pvk));
            float2 v1 = __ldg((const float2*)(pvk + 8));
            bv[ks].x = cvt_h2(v0.x, v0.y);
            bv[ks].y = cvt_h2(v1.x, v1.y);
        }

        float accz[2][4], accv[2][4];             // [mt][frag]
        #pragma unroll
        for (int mt = 0; mt < 2; mt++)
            #pragma unroll
            for (int e = 0; e < 4; e++) { accz[mt][e] = 0.f; accv[mt][e] = 0.f; }

        #pragma unroll
        for (int mt = 0; mt < 2; mt++)
            #pragma unroll
            for (int ks = 0; ks < 2; ks++) {
                mma_f16(accz[mt], a1[mt][ks], bz[ks].x, bz[ks].y);  // h1 pass
                mma_f16(accv[mt], a1[mt][ks], bv[ks].x, bv[ks].y);
                mma_f16(accz[mt], a2[mt][ks], bz[ks].x, bz[ks].y);  // h2 pass
                mma_f16(accv[mt], a2[mt][ks], bv[ks].x, bv[ks].y);
            }

        // --- epilogue fold for this p-slab ---
        const int kbase = kh * 64 + p * 8 + 2 * (lane & 3);
        const float2 b1p = __ldg((const float2*)(b1 + kbase));
        const float2 csp = *(const float2*)(s_cs + kbase);
        #pragma unroll
        for (int j = 0; j < 2; j++) {
            const float b1k = j ? b1p.y : b1p.x;
            const float ck  = j ? csp.y : csp.x;
            #pragma unroll
            for (int mt = 0; mt < 2; mt++)
                #pragma unroll
                for (int rs = 0; rs < 2; rs++) {
                    float z = accz[mt][rs * 2 + j] + b1k;
                    float v = accv[mt][rs * 2 + j];
                    float h = tanh_ap(z);
                    float g = fmaf(-h, h, 1.0f);
                    float& ps = psum[mt * 2 + rs];
                    ps = fmaf(g, ck, ps);
                    ps = fmaf(-h, v, ps);
                }
        }
    }

    // quad reduction over the 4 lanes sharing the same rows
    #pragma unroll
    for (int i = 0; i < 4; i++) {
        psum[i] += __shfl_xor_sync(0xFFFFFFFFu, psum[i], 1);
        psum[i] += __shfl_xor_sync(0xFFFFFFFFu, psum[i], 2);
    }
    if ((lane & 3) == 0) {
        const int rbase = mh * 32 + (lane >> 2);
        s_part[rbase +  0][kh] = psum[0];
        s_part[rbase +  8][kh] = psum[1];
        s_part[rbase + 16][kh] = psum[2];
        s_part[rbase + 24][kh] = psum[3];
    }
    __syncthreads();

    if (tid < TILE_M)
        out[row0 + tid] = s_base[tid] + s_part[tid][0] + s_part[tid][1];
}

extern "C" void kernel_launch(void* const* d_in, const int* in_sizes, int n_in,
                              void* d_out, int out_size)
{
    const float* x     = (const float*)d_in[0];
    const float* W1    = (const float*)d_in[1];
    const float* b1    = (const float*)d_in[2];
    const float* W2    = (const float*)d_in[3];
    const float* b2    = (const float*)d_in[4];
    const float* theta = (const float*)d_in[5];
    float*       out   = (float*)d_out;

    const int nrows = in_sizes[0] / D;          // 65536
    const int grid  = nrows / TILE_M;           // 1024

    stein_main<<<grid, THREADS>>>(x, W1, b1, W2, b2, theta, out);
}